// round 6
// baseline (speedup 1.0000x reference)
#include <cuda_runtime.h>
#include <cuda_bf16.h>
#include <cstdint>

#define N_NODES 100000
#define F1 128
#define F2 64
#define EMAX 1600000

// Scratch (device globals: allocation-free, graph-safe)
__device__ float g_bufA[N_NODES * F2];   // GEMM output (pre-aggregation messages)
__device__ float g_bufC[N_NODES * F2];   // hidden activations h1
__device__ float g_rso[N_NODES];         // rsqrt(deg_out)
__device__ float g_rsi[N_NODES];         // rsqrt(deg_in)
__device__ int   g_dego[N_NODES];
__device__ int   g_degi[N_NODES];
__device__ int   g_off[N_NODES];         // segment start per dst node
__device__ int   g_cur[N_NODES];         // fill cursor per dst node
__device__ int   g_sorted[EMAX];         // src indices grouped by dst
__device__ int   g_total;                // segment allocator

// ---------------------------------------------------------------------------
__global__ void k_zero() {
    int i = blockIdx.x * blockDim.x + threadIdx.x;
    if (i < N_NODES) { g_dego[i] = 0; g_degi[i] = 0; }
    if (i == 0) g_total = 0;
}

// 4 edges per thread, int4 loads
__global__ void k_degree(const int* __restrict__ src, const int* __restrict__ dst, int E) {
    int t = blockIdx.x * blockDim.x + threadIdx.x;
    int i = t * 4;
    if (i + 3 < E) {
        int4 s = __ldg((const int4*)(src + i));
        int4 d = __ldg((const int4*)(dst + i));
        atomicAdd(&g_dego[s.x], 1); atomicAdd(&g_degi[d.x], 1);
        atomicAdd(&g_dego[s.y], 1); atomicAdd(&g_degi[d.y], 1);
        atomicAdd(&g_dego[s.z], 1); atomicAdd(&g_degi[d.z], 1);
        atomicAdd(&g_dego[s.w], 1); atomicAdd(&g_degi[d.w], 1);
    } else {
        for (int k = i; k < E; ++k) {
            atomicAdd(&g_dego[src[k]], 1);
            atomicAdd(&g_degi[dst[k]], 1);
        }
    }
}

// Segment allocation (warp scan + 1 atomic/warp) fused with norm computation.
__global__ void k_alloc() {
    int i = blockIdx.x * blockDim.x + threadIdx.x;
    int lane = threadIdx.x & 31;
    int deg = 0, dego = 0;
    if (i < N_NODES) { deg = g_degi[i]; dego = g_dego[i]; }
    int incl = deg;
#pragma unroll
    for (int o = 1; o < 32; o <<= 1) {
        int n = __shfl_up_sync(0xFFFFFFFFu, incl, o);
        if (lane >= o) incl += n;
    }
    int wtotal = __shfl_sync(0xFFFFFFFFu, incl, 31);
    int base = 0;
    if (lane == 0) base = atomicAdd(&g_total, wtotal);
    base = __shfl_sync(0xFFFFFFFFu, base, 0);
    if (i < N_NODES) {
        int off = base + incl - deg;
        g_off[i] = off;
        g_cur[i] = off;
        g_rsi[i] = rsqrtf((float)max(deg, 1));
        g_rso[i] = rsqrtf((float)max(dego, 1));
    }
}

// Group src indices by dst (counting-sort placement), 4 edges per thread.
__global__ void k_bin(const int* __restrict__ src, const int* __restrict__ dst, int E) {
    int t = blockIdx.x * blockDim.x + threadIdx.x;
    int i = t * 4;
    if (i + 3 < E) {
        int4 s = __ldg((const int4*)(src + i));
        int4 d = __ldg((const int4*)(dst + i));
        g_sorted[atomicAdd(&g_cur[d.x], 1)] = s.x;
        g_sorted[atomicAdd(&g_cur[d.y], 1)] = s.y;
        g_sorted[atomicAdd(&g_cur[d.z], 1)] = s.z;
        g_sorted[atomicAdd(&g_cur[d.w], 1)] = s.w;
    } else {
        for (int k = i; k < E; ++k)
            g_sorted[atomicAdd(&g_cur[dst[k]], 1)] = src[k];
    }
}

// ---------------------------------------------------------------------------
// Y[r, :] = (X[r, :] @ W) * g_rso[r]    X:[M,K]  W:[K,64]  Y:[M,64]
// 128-row tile, 256 threads, 8x4 register blocking. x-row loads are
// warp-broadcast (address depends only on ty) -> LDS well under FMA cost.
template <int K>
__global__ void __launch_bounds__(256, 2)
k_gemm_scale(const float* __restrict__ X, const float* __restrict__ W,
             float* __restrict__ Y, int M) {
    extern __shared__ float smem[];
    float* sW = smem;            // [K][64]
    float* sX = smem + K * 64;   // [128][K]

    const int tid = threadIdx.x;
    const int row0 = blockIdx.x * 128;

    // Load W (whole matrix)
    for (int i = tid; i < K * 16; i += 256)
        ((float4*)sW)[i] = ((const float4*)W)[i];

    // Load X tile (zero-fill out-of-range rows)
    const int RV = K / 4;  // float4 per row
    for (int i = tid; i < 128 * RV; i += 256) {
        int r = i / RV, c = i % RV;
        float4 v = make_float4(0.f, 0.f, 0.f, 0.f);
        if (row0 + r < M)
            v = ((const float4*)(X + (size_t)(row0 + r) * K))[c];
        ((float4*)sX)[i] = v;
    }
    __syncthreads();

    const int tx = tid & 15;   // col group (4 cols)
    const int ty = tid >> 4;   // row group (8 rows)

    float acc[8][4];
#pragma unroll
    for (int j = 0; j < 8; j++)
#pragma unroll
        for (int c = 0; c < 4; c++) acc[j][c] = 0.0f;

    for (int k4 = 0; k4 < K / 4; ++k4) {
        float4 xv[8];
#pragma unroll
        for (int j = 0; j < 8; j++)
            xv[j] = ((const float4*)(sX + (ty * 8 + j) * K))[k4];
#pragma unroll
        for (int kk = 0; kk < 4; kk++) {
            float4 wv = ((const float4*)(sW + (k4 * 4 + kk) * 64))[tx];
#pragma unroll
            for (int j = 0; j < 8; j++) {
                const float* xp = (const float*)&xv[j];
                float xs = xp[kk];
                acc[j][0] += xs * wv.x;
                acc[j][1] += xs * wv.y;
                acc[j][2] += xs * wv.z;
                acc[j][3] += xs * wv.w;
            }
        }
    }

#pragma unroll
    for (int j = 0; j < 8; j++) {
        int gr = row0 + ty * 8 + j;
        if (gr < M) {
            float s = g_rso[gr];
            float4 o = make_float4(acc[j][0] * s, acc[j][1] * s, acc[j][2] * s, acc[j][3] * s);
            ((float4*)(Y + (size_t)gr * 64))[tx] = o;
        }
    }
}

// ---------------------------------------------------------------------------
// Gather-aggregate per dst node (no atomics), fused epilogue:
//   out[n] = act( rsi[n] * sum_{s in seg(n)} A[s] + bias )
template <bool RELU>
__global__ void k_agg(const float* __restrict__ Asrc, const float* __restrict__ bias,
                      float* __restrict__ out) {
    int idx = blockIdx.x * blockDim.x + threadIdx.x;
    if (idx >= N_NODES * 16) return;
    int node = idx >> 4;
    int c = idx & 15;

    int base = g_off[node];
    int deg  = g_degi[node];
    int end  = base + deg;

    const float4* A = (const float4*)Asrc;
    float4 acc = make_float4(0.f, 0.f, 0.f, 0.f);

    int i = base;
    for (; i + 4 <= end; i += 4) {
        int s0 = __ldg(g_sorted + i);
        int s1 = __ldg(g_sorted + i + 1);
        int s2 = __ldg(g_sorted + i + 2);
        int s3 = __ldg(g_sorted + i + 3);
        float4 v0 = __ldg(A + (size_t)s0 * 16 + c);
        float4 v1 = __ldg(A + (size_t)s1 * 16 + c);
        float4 v2 = __ldg(A + (size_t)s2 * 16 + c);
        float4 v3 = __ldg(A + (size_t)s3 * 16 + c);
        acc.x += (v0.x + v1.x) + (v2.x + v3.x);
        acc.y += (v0.y + v1.y) + (v2.y + v3.y);
        acc.z += (v0.z + v1.z) + (v2.z + v3.z);
        acc.w += (v0.w + v1.w) + (v2.w + v3.w);
    }
    for (; i < end; ++i) {
        int s = __ldg(g_sorted + i);
        float4 v = __ldg(A + (size_t)s * 16 + c);
        acc.x += v.x; acc.y += v.y; acc.z += v.z; acc.w += v.w;
    }

    float sc = g_rsi[node];
    float4 bb = __ldg(((const float4*)bias) + c);
    float4 o;
    o.x = acc.x * sc + bb.x;
    o.y = acc.y * sc + bb.y;
    o.z = acc.z * sc + bb.z;
    o.w = acc.w * sc + bb.w;
    if (RELU) {
        o.x = fmaxf(o.x, 0.f); o.y = fmaxf(o.y, 0.f);
        o.z = fmaxf(o.z, 0.f); o.w = fmaxf(o.w, 0.f);
    }
    ((float4*)out)[idx] = o;
}

// ---------------------------------------------------------------------------
extern "C" void kernel_launch(void* const* d_in, const int* in_sizes, int n_in,
                              void* d_out, int out_size) {
    const float* x   = (const float*)d_in[0];
    const int*   src = (const int*)  d_in[1];
    const int*   dst = (const int*)  d_in[2];
    const float* W1  = (const float*)d_in[3];
    const float* b1  = (const float*)d_in[4];
    const float* W2  = (const float*)d_in[5];
    const float* b2  = (const float*)d_in[6];
    float* out = (float*)d_out;

    const int E = in_sizes[1];
    const int M = in_sizes[0] / F1;  // == N_NODES

    void* pA = nullptr; void* pC = nullptr;
    cudaGetSymbolAddress(&pA, g_bufA);
    cudaGetSymbolAddress(&pC, g_bufC);

    // Side stream + events for fork/join (created once on first, non-captured
    // call; no device memory involved — graph-capture legal pattern).
    static cudaStream_t s2 = nullptr;
    static cudaEvent_t evFork = nullptr, evJoin = nullptr;
    if (!s2) {
        cudaStreamCreateWithFlags(&s2, cudaStreamNonBlocking);
        cudaEventCreateWithFlags(&evFork, cudaEventDisableTiming);
        cudaEventCreateWithFlags(&evJoin, cudaEventDisableTiming);
    }

    const int T = 256;
    const int smem1 = (F1 * 64 + 128 * F1) * 4;  // 96 KB
    const int smem2 = (F2 * 64 + 128 * F2) * 4;  // 48 KB
    cudaFuncSetAttribute(k_gemm_scale<F1>, cudaFuncAttributeMaxDynamicSharedMemorySize, smem1);
    cudaFuncSetAttribute(k_gemm_scale<F2>, cudaFuncAttributeMaxDynamicSharedMemorySize, smem2);

    const int E4 = (E + 3) / 4;

    // Main stream: zero -> degree -> alloc (GEMM1 epilogue needs g_rso)
    k_zero<<<(N_NODES + T - 1) / T, T>>>();
    k_degree<<<(E4 + T - 1) / T, T>>>(src, dst, E);
    k_alloc<<<(N_NODES + T - 1) / T, T>>>();

    // Fork: k_bin (latency-bound, only needed by k_agg) overlaps GEMM1.
    cudaEventRecord(evFork, 0);
    cudaStreamWaitEvent(s2, evFork, 0);
    k_bin<<<(E4 + T - 1) / T, T, 0, s2>>>(src, dst, E);
    cudaEventRecord(evJoin, s2);

    // Main stream: layer-1 GEMM (compute-bound), concurrent with k_bin.
    k_gemm_scale<F1><<<(M + 127) / 128, 256, smem1>>>(x, W1, (float*)pA, M);

    // Join before aggregation.
    cudaStreamWaitEvent(0, evJoin, 0);

    // h1 = relu(rsi * sum A[srcs] + b1)
    k_agg<true><<<(N_NODES * 16 + T - 1) / T, T>>>((const float*)pA, b1, (float*)pC);
    // layer-2 GEMM: A = (h1 @ W2) * rso
    k_gemm_scale<F2><<<(M + 127) / 128, 256, smem2>>>((const float*)pC, W2, (float*)pA, M);
    // out = rsi * sum A[srcs] + b2
    k_agg<false><<<(N_NODES * 16 + T - 1) / T, T>>>((const float*)pA, b2, out);
}